// round 1
// baseline (speedup 1.0000x reference)
#include <cuda_runtime.h>

#define B_ 2048
#define T_ 128
#define S_ 256
#define V_ 29
#define E_ 32
#define H_ 64

struct Smem {
    float enc_t[H_ * S_];   // transposed encoder tile [h][s]
    float fc[V_ * 128];     // fc_W rows (128 = 2H)
    float emb[V_ * E_];     // embedding table
    float x[96];            // [emb(32) | context(64)]  (16B aligned by offset)
    float h[H_];
    float c[H_];
    float attn[S_];         // unnormalized exp(score - max)
    float gates[4 * H_];
    float red_max[8];
    float red_sum[8];
    float fcb[32];
    int   y[T_];
};

__global__ __launch_bounds__(256, 1)
void decoder_kernel(const int*   __restrict__ y,
                    const float* __restrict__ h0,
                    const float* __restrict__ c0,
                    const float* __restrict__ enc,
                    const float* __restrict__ emb_table,
                    const float* __restrict__ W_ih,
                    const float* __restrict__ W_hh,
                    const float* __restrict__ b_ih,
                    const float* __restrict__ b_hh,
                    const float* __restrict__ fc_W,
                    const float* __restrict__ fc_b,
                    float*       __restrict__ out)
{
    extern __shared__ Smem sm[];
    Smem* s = sm;
    const int tid  = threadIdx.x;
    const int b    = blockIdx.x;
    const int lane = tid & 31;
    const int wid  = tid >> 5;

    // ---- One-time loads -------------------------------------------------
    // Gate weights: thread g owns row g of W_ih (96) and W_hh (64) in registers.
    float4 wih[24];
    {
        const float4* p = (const float4*)(W_ih + tid * 96);
        #pragma unroll
        for (int k = 0; k < 24; k++) wih[k] = p[k];
    }
    float4 whh[16];
    {
        const float4* p = (const float4*)(W_hh + tid * 64);
        #pragma unroll
        for (int k = 0; k < 16; k++) whh[k] = p[k];
    }
    const float bias = b_ih[tid] + b_hh[tid];

    // Encoder tile -> SMEM, transposed to [h][s] (coalesced global reads).
    {
        const float* ge = enc + (size_t)b * (S_ * H_);
        for (int i = tid; i < S_ * H_; i += 256) {
            int ss = i >> 6, hh = i & 63;
            s->enc_t[hh * S_ + ss] = ge[i];
        }
    }
    for (int i = tid; i < V_ * 128; i += 256) s->fc[i]  = fc_W[i];
    for (int i = tid; i < V_ * E_;  i += 256) s->emb[i] = emb_table[i];
    if (tid < H_) { s->h[tid] = h0[b * H_ + tid]; s->c[tid] = c0[b * H_ + tid]; }
    if (tid < T_) s->y[tid]  = y[b * T_ + tid];
    if (tid < V_) s->fcb[tid] = fc_b[tid];
    __syncthreads();

    float* outb = out + (size_t)b * T_ * V_;

    // ---- Time loop ------------------------------------------------------
    #pragma unroll 1
    for (int t = 0; t < T_; t++) {
        // Embedding for this step -> x[0..31] (disjoint from regions read late
        // in the previous iteration; made visible to gates by the sync below).
        if (tid < E_) s->x[tid] = s->emb[s->y[t] * E_ + tid];

        // A: scores[s=tid] = sum_h enc_t[h][tid] * h_prev[h]
        float a0 = 0.f, a1 = 0.f, a2 = 0.f, a3 = 0.f;
        #pragma unroll 4
        for (int h = 0; h < H_; h += 4) {
            a0 += s->enc_t[(h + 0) * S_ + tid] * s->h[h + 0];
            a1 += s->enc_t[(h + 1) * S_ + tid] * s->h[h + 1];
            a2 += s->enc_t[(h + 2) * S_ + tid] * s->h[h + 2];
            a3 += s->enc_t[(h + 3) * S_ + tid] * s->h[h + 3];
        }
        const float score = (a0 + a1) + (a2 + a3);

        // B: softmax (unnormalized exp; 1/sum folded into context)
        float m = score;
        #pragma unroll
        for (int o = 16; o > 0; o >>= 1) m = fmaxf(m, __shfl_xor_sync(0xffffffffu, m, o));
        if (lane == 0) s->red_max[wid] = m;
        __syncthreads();                                  // sync1
        float mall = s->red_max[0];
        #pragma unroll
        for (int w = 1; w < 8; w++) mall = fmaxf(mall, s->red_max[w]);
        const float e = __expf(score - mall);
        s->attn[tid] = e;
        float sum = e;
        #pragma unroll
        for (int o = 16; o > 0; o >>= 1) sum += __shfl_xor_sync(0xffffffffu, sum, o);
        if (lane == 0) s->red_sum[wid] = sum;
        __syncthreads();                                  // sync2
        float tot = 0.f;
        #pragma unroll
        for (int w = 0; w < 8; w++) tot += s->red_sum[w];
        const float inv = 1.0f / tot;

        // C: context[h] -> x[32+h]; warp wid handles rows wid*8 .. wid*8+7
        float av[8];
        #pragma unroll
        for (int k = 0; k < 8; k++) av[k] = s->attn[lane + 32 * k];
        #pragma unroll 2
        for (int r = 0; r < 8; r++) {
            const int h = wid * 8 + r;
            const float* er = s->enc_t + h * S_ + lane;
            float p = 0.f;
            #pragma unroll
            for (int k = 0; k < 8; k++) p += av[k] * er[32 * k];
            #pragma unroll
            for (int o = 16; o > 0; o >>= 1) p += __shfl_xor_sync(0xffffffffu, p, o);
            if (lane == 0) s->x[E_ + h] = p * inv;
        }
        __syncthreads();                                  // sync3 (x complete)

        // D: gates[g=tid] = bias + x.W_ih[g] + h.W_hh[g]  (weights in regs,
        // operands via broadcast LDS.128)
        float g0 = bias, g1 = 0.f, g2 = 0.f, g3 = 0.f;
        {
            const float4* x4 = (const float4*)s->x;
            #pragma unroll
            for (int k = 0; k < 24; k++) {
                const float4 xv = x4[k];
                g0 += xv.x * wih[k].x; g1 += xv.y * wih[k].y;
                g2 += xv.z * wih[k].z; g3 += xv.w * wih[k].w;
            }
            const float4* h4 = (const float4*)s->h;
            #pragma unroll
            for (int k = 0; k < 16; k++) {
                const float4 hv = h4[k];
                g0 += hv.x * whh[k].x; g1 += hv.y * whh[k].y;
                g2 += hv.z * whh[k].z; g3 += hv.w * whh[k].w;
            }
        }
        s->gates[tid] = (g0 + g1) + (g2 + g3);
        __syncthreads();                                  // sync4

        // E: LSTM cell update (i,f,g,o order)
        if (tid < H_) {
            const float gi = s->gates[tid];
            const float gf = s->gates[H_ + tid];
            const float gg = s->gates[2 * H_ + tid];
            const float go = s->gates[3 * H_ + tid];
            const float si = 1.0f / (1.0f + __expf(-gi));
            const float sf = 1.0f / (1.0f + __expf(-gf));
            const float so = 1.0f / (1.0f + __expf(-go));
            const float cn = sf * s->c[tid] + si * tanhf(gg);
            s->c[tid] = cn;
            s->h[tid] = so * tanhf(cn);
        }
        __syncthreads();                                  // sync5

        // F: logits[v] = [h_new | context] . fc_W[v] + fc_b[v]; warp per v
        #pragma unroll
        for (int q = 0; q < 4; q++) {
            const int v = q * 8 + wid;
            if (v < V_) {
                const float* fr = s->fc + v * 128;
                float p = fr[lane]      * s->h[lane]
                        + fr[lane + 32] * s->h[lane + 32]
                        + fr[lane + 64] * s->x[E_ + lane]
                        + fr[lane + 96] * s->x[E_ + 32 + lane];
                #pragma unroll
                for (int o = 16; o > 0; o >>= 1) p += __shfl_xor_sync(0xffffffffu, p, o);
                if (lane == 0) outb[t * V_ + v] = p + s->fcb[v];
            }
        }
        // No barrier needed here: the only cross-warp hazards into the next
        // iteration are fenced by sync1/sync2 before any re-written buffer
        // (attn, red_*, x[32..95], gates) is read or overwritten.
    }
}

extern "C" void kernel_launch(void* const* d_in, const int* in_sizes, int n_in,
                              void* d_out, int out_size) {
    const int*   y         = (const int*)  d_in[0];
    const float* h0        = (const float*)d_in[1];
    const float* c0        = (const float*)d_in[2];
    const float* enc       = (const float*)d_in[3];
    const float* emb_table = (const float*)d_in[4];
    const float* W_ih      = (const float*)d_in[5];
    const float* W_hh      = (const float*)d_in[6];
    const float* b_ih      = (const float*)d_in[7];
    const float* b_hh      = (const float*)d_in[8];
    const float* fc_W      = (const float*)d_in[9];
    const float* fc_b      = (const float*)d_in[10];
    float* out = (float*)d_out;

    cudaFuncSetAttribute(decoder_kernel,
                         cudaFuncAttributeMaxDynamicSharedMemorySize,
                         (int)sizeof(Smem));
    decoder_kernel<<<B_, 256, sizeof(Smem)>>>(
        y, h0, c0, enc, emb_table, W_ih, W_hh, b_ih, b_hh, fc_W, fc_b, out);
}

// round 4
// speedup vs baseline: 1.5490x; 1.5490x over previous
#include <cuda_runtime.h>

#define B_ 2048
#define T_ 128
#define S_ 256
#define V_ 29
#define E_ 32
#define H_ 64
#define H2 32          // H_/2 pairs
#define PITCH 257      // float2 row pitch (bank-conflict pad)

typedef unsigned long long ull;

__device__ __forceinline__ ull fma2(ull a, ull b, ull c) {
    ull d; asm("fma.rn.f32x2 %0, %1, %2, %3;" : "=l"(d) : "l"(a), "l"(b), "l"(c));
    return d;
}
__device__ __forceinline__ ull pack2(float x, float y) {
    ull d; asm("mov.b64 %0, {%1, %2};" : "=l"(d)
               : "r"(__float_as_uint(x)), "r"(__float_as_uint(y)));
    return d;
}
__device__ __forceinline__ float2 unpack2(ull v) {
    unsigned lo, hi; asm("mov.b64 {%0, %1}, %2;" : "=r"(lo), "=r"(hi) : "l"(v));
    return make_float2(__uint_as_float(lo), __uint_as_float(hi));
}
__device__ __forceinline__ float sigmoid_f(float x) { return 1.0f / (1.0f + __expf(-x)); }
__device__ __forceinline__ float tanh_f(float x)    { return 1.0f - 2.0f / (__expf(2.0f * x) + 1.0f); }

struct Smem {
    float2 enc2[2][H2][PITCH];   // [bat][h-pair][s]
    float  fc[V_ * 128];
    float  emb[V_ * E_];
    float  x[2][96];             // [emb(32) | context(64)] per batch, 8B aligned
    float  h[2][H_];
    float  c[2][H_];
    float  attn[2][S_];
    float  gates[2][4 * H_];
    float  red_max[2][8];
    float  red_sum[2][8];
    float  fcb[32];
    int    y[2][T_];
};

__global__ __launch_bounds__(256, 1)
void decoder_kernel(const int*   __restrict__ y,
                    const float* __restrict__ h0,
                    const float* __restrict__ c0,
                    const float* __restrict__ enc,
                    const float* __restrict__ emb_table,
                    const float* __restrict__ W_ih,
                    const float* __restrict__ W_hh,
                    const float* __restrict__ b_ih,
                    const float* __restrict__ b_hh,
                    const float* __restrict__ fc_W,
                    const float* __restrict__ fc_b,
                    float*       __restrict__ out)
{
    extern __shared__ Smem sm[];
    Smem* s = sm;
    const int tid  = threadIdx.x;
    const int lane = tid & 31;
    const int wid  = tid >> 5;
    const int bA = 2 * blockIdx.x;      // batch 0 of this CTA
    const int bB = bA + 1;              // batch 1

    // ---- One-time loads -------------------------------------------------
    // Gate weights packed along K: thread g owns row g. 80 u64 = 160 regs.
    ull wih[48], whh[32];
    {
        const ull* p = (const ull*)(W_ih + tid * 96);
        #pragma unroll
        for (int k = 0; k < 48; k++) wih[k] = p[k];
        const ull* q = (const ull*)(W_hh + tid * 64);
        #pragma unroll
        for (int k = 0; k < 32; k++) whh[k] = q[k];
    }
    const float bias = b_ih[tid] + b_hh[tid];

    // Encoder tiles: global [b][s][h] -> smem float2 [bat][h/2][s]
    #pragma unroll
    for (int bat = 0; bat < 2; bat++) {
        const int b = bA + bat;
        const float2* ge = (const float2*)(enc + (size_t)b * (S_ * H_));
        for (int i = tid; i < S_ * H2; i += 256) {
            int ss = i >> 5, p = i & 31;            // p fastest -> coalesced reads
            s->enc2[bat][p][ss] = ge[ss * H2 + p];
        }
    }
    for (int i = tid; i < V_ * 128; i += 256) s->fc[i]  = fc_W[i];
    for (int i = tid; i < V_ * E_;  i += 256) s->emb[i] = emb_table[i];
    if (tid < 2 * H_) {
        int bat = tid >> 6, j = tid & 63;
        s->h[bat][j] = h0[(bA + bat) * H_ + j];
        s->c[bat][j] = c0[(bA + bat) * H_ + j];
    }
    if (tid < T_) { s->y[0][tid] = y[bA * T_ + tid]; s->y[1][tid] = y[bB * T_ + tid]; }
    if (tid < V_) s->fcb[tid] = fc_b[tid];
    __syncthreads();

    float* outA = out + (size_t)bA * T_ * V_;
    float* outB = out + (size_t)bB * T_ * V_;

    // ---- Time loop ------------------------------------------------------
    #pragma unroll 1
    for (int t = 0; t < T_; t++) {
        // Embedding for this step -> x[bat][0..31]
        if (tid < 2 * E_) {
            int bat = tid >> 5, j = tid & 31;
            s->x[bat][j] = s->emb[s->y[bat][t] * E_ + j];
        }

        // A: scores[s=tid] for both batches (packed over h-pairs)
        float score0, score1;
        {
            const ull* e0 = (const ull*)&s->enc2[0][0][0];
            const ull* e1 = (const ull*)&s->enc2[1][0][0];
            const ull* hp0 = (const ull*)s->h[0];
            const ull* hp1 = (const ull*)s->h[1];
            ull a0 = 0, a1 = 0, c0p = 0, c1p = 0;
            #pragma unroll
            for (int k = 0; k < H2; k += 2) {
                a0  = fma2(e0[k * PITCH + tid],       hp0[k],     a0);
                a1  = fma2(e1[k * PITCH + tid],       hp1[k],     a1);
                c0p = fma2(e0[(k + 1) * PITCH + tid], hp0[k + 1], c0p);
                c1p = fma2(e1[(k + 1) * PITCH + tid], hp1[k + 1], c1p);
            }
            float2 v0 = unpack2(a0), w0 = unpack2(c0p);
            float2 v1 = unpack2(a1), w1 = unpack2(c1p);
            score0 = (v0.x + v0.y) + (w0.x + w0.y);
            score1 = (v1.x + v1.y) + (w1.x + w1.y);
        }

        // B: softmax (unnormalized exp; 1/sum folded into context)
        float m0 = score0, m1 = score1;
        #pragma unroll
        for (int o = 16; o > 0; o >>= 1) {
            m0 = fmaxf(m0, __shfl_xor_sync(0xffffffffu, m0, o));
            m1 = fmaxf(m1, __shfl_xor_sync(0xffffffffu, m1, o));
        }
        if (lane == 0) { s->red_max[0][wid] = m0; s->red_max[1][wid] = m1; }
        __syncthreads();                                  // sync1
        float mall0 = s->red_max[0][0], mall1 = s->red_max[1][0];
        #pragma unroll
        for (int w = 1; w < 8; w++) {
            mall0 = fmaxf(mall0, s->red_max[0][w]);
            mall1 = fmaxf(mall1, s->red_max[1][w]);
        }
        const float e0v = __expf(score0 - mall0);
        const float e1v = __expf(score1 - mall1);
        s->attn[0][tid] = e0v; s->attn[1][tid] = e1v;
        float s0 = e0v, s1 = e1v;
        #pragma unroll
        for (int o = 16; o > 0; o >>= 1) {
            s0 += __shfl_xor_sync(0xffffffffu, s0, o);
            s1 += __shfl_xor_sync(0xffffffffu, s1, o);
        }
        if (lane == 0) { s->red_sum[0][wid] = s0; s->red_sum[1][wid] = s1; }
        __syncthreads();                                  // sync2
        float tot0 = 0.f, tot1 = 0.f;
        #pragma unroll
        for (int w = 0; w < 8; w++) { tot0 += s->red_sum[0][w]; tot1 += s->red_sum[1][w]; }
        const float inv0 = 1.0f / tot0;
        const float inv1 = 1.0f / tot1;

        // C: context -> x[bat][32..95]; warp handles h-pairs wid*4..wid*4+3
        #pragma unroll
        for (int bat = 0; bat < 2; bat++) {
            const float invb = bat ? inv1 : inv0;
            ull ap[8];
            #pragma unroll
            for (int j = 0; j < 8; j++) {
                float a = s->attn[bat][lane + 32 * j];
                ap[j] = pack2(a, a);
            }
            const ull* eb = (const ull*)&s->enc2[bat][0][0];
            ull acc[4] = {0, 0, 0, 0};
            #pragma unroll
            for (int p = 0; p < 4; p++) {
                const int base = (wid * 4 + p) * PITCH + lane;
                #pragma unroll
                for (int j = 0; j < 8; j++)
                    acc[p] = fma2(eb[base + 32 * j], ap[j], acc[p]);
            }
            #pragma unroll
            for (int p = 0; p < 4; p++) {
                float2 v = unpack2(acc[p]);
                float cx = v.x, cy = v.y;
                #pragma unroll
                for (int o = 16; o > 0; o >>= 1) {
                    cx += __shfl_xor_sync(0xffffffffu, cx, o);
                    cy += __shfl_xor_sync(0xffffffffu, cy, o);
                }
                if (lane == 0) {
                    const int pp = wid * 4 + p;
                    s->x[bat][E_ + 2 * pp]     = cx * invb;
                    s->x[bat][E_ + 2 * pp + 1] = cy * invb;
                }
            }
        }
        __syncthreads();                                  // sync3 (x complete)

        // D: gates for both batches, shared weight registers, packed FMA
        {
            const ull* x0 = (const ull*)s->x[0];
            const ull* x1 = (const ull*)s->x[1];
            ull a0 = 0, a1 = 0;
            #pragma unroll
            for (int k = 0; k < 48; k++) {
                a0 = fma2(x0[k], wih[k], a0);
                a1 = fma2(x1[k], wih[k], a1);
            }
            const ull* hh0 = (const ull*)s->h[0];
            const ull* hh1 = (const ull*)s->h[1];
            #pragma unroll
            for (int k = 0; k < 32; k++) {
                a0 = fma2(hh0[k], whh[k], a0);
                a1 = fma2(hh1[k], whh[k], a1);
            }
            float2 v0 = unpack2(a0), v1 = unpack2(a1);
            s->gates[0][tid] = bias + v0.x + v0.y;
            s->gates[1][tid] = bias + v1.x + v1.y;
        }
        __syncthreads();                                  // sync4

        // E: LSTM cell update for both batches (i,f,g,o)
        if (tid < 2 * H_) {
            const int bat = tid >> 6, j = tid & 63;
            const float gi = s->gates[bat][j];
            const float gf = s->gates[bat][H_ + j];
            const float gg = s->gates[bat][2 * H_ + j];
            const float go = s->gates[bat][3 * H_ + j];
            const float cn = sigmoid_f(gf) * s->c[bat][j] + sigmoid_f(gi) * tanh_f(gg);
            s->c[bat][j] = cn;
            s->h[bat][j] = sigmoid_f(go) * tanh_f(cn);
        }
        __syncthreads();                                  // sync5

        // F: logits; 58 warp-tasks (2 batches x 29 vocab) over 8 warps
        #pragma unroll
        for (int q = 0; q < 8; q++) {
            const int task = q * 8 + wid;
            if (task < 2 * V_) {
                const int bat = (task >= V_) ? 1 : 0;
                const int v   = task - V_ * bat;
                const float* fr = s->fc + v * 128;
                const float* hb = s->h[bat];
                const float* cb = s->x[bat] + E_;
                float p = fr[lane]      * hb[lane]
                        + fr[lane + 32] * hb[lane + 32]
                        + fr[lane + 64] * cb[lane]
                        + fr[lane + 96] * cb[lane + 32];
                #pragma unroll
                for (int o = 16; o > 0; o >>= 1) p += __shfl_xor_sync(0xffffffffu, p, o);
                if (lane == 0) {
                    float* ob = bat ? outB : outA;
                    ob[t * V_ + v] = p + s->fcb[v];
                }
            }
        }
        // No trailing barrier: next-iteration writes before sync1 touch only
        // x[bat][0..31] and red_max, which phase F does not read.
    }
}

extern "C" void kernel_launch(void* const* d_in, const int* in_sizes, int n_in,
                              void* d_out, int out_size) {
    const int*   y         = (const int*)  d_in[0];
    const float* h0        = (const float*)d_in[1];
    const float* c0        = (const float*)d_in[2];
    const float* enc       = (const float*)d_in[3];
    const float* emb_table = (const float*)d_in[4];
    const float* W_ih      = (const float*)d_in[5];
    const float* W_hh      = (const float*)d_in[6];
    const float* b_ih      = (const float*)d_in[7];
    const float* b_hh      = (const float*)d_in[8];
    const float* fc_W      = (const float*)d_in[9];
    const float* fc_b      = (const float*)d_in[10];
    float* out = (float*)d_out;

    cudaFuncSetAttribute(decoder_kernel,
                         cudaFuncAttributeMaxDynamicSharedMemorySize,
                         (int)sizeof(Smem));
    decoder_kernel<<<B_ / 2, 256, sizeof(Smem)>>>(
        y, h0, c0, enc, emb_table, W_ih, W_hh, b_ih, b_hh, fc_W, fc_b, out);
}